// round 1
// baseline (speedup 1.0000x reference)
#include <cuda_runtime.h>
#include <math.h>

#define N_NODES 50000
#define N_EDGES 600000
#define H 128
#define H13 (13 * H)
#define LOG17 2.8332133440562162f

// ---------------- scratch (static device globals; no allocation) ----------------
__device__ float g_xd[(size_t)N_NODES * H];    // x @ Wpre[0:H]    (reused as ys)
__device__ float g_xs[(size_t)N_NODES * H];    // x @ Wpre[H:2H]   (reused as yd)
__device__ float g_h[(size_t)N_EDGES * H];     // per-edge message (reused as z)
__device__ float g_A13[(size_t)N_NODES * H13]; // cat[x, scaled]
__device__ float g_outb[(size_t)N_NODES * H];  // pre-BN node output
__device__ float g_Wef[H * H];                 // We @ Wpre[2H:3H]
__device__ float g_W13[H13 * H];               // Wpost @ Wlin
__device__ float g_bh[H];
__device__ float g_b13[H];
__device__ int   g_deg[N_NODES];
__device__ int   g_off[N_NODES + 1];
__device__ int   g_cur[N_NODES];
__device__ int   g_perm[N_EDGES];
__device__ float g_bnsum[H];
__device__ float g_bnsq[H];
__device__ float g_mu[H];
__device__ float g_istd[H];

// ---------------- generic 128-wide GEMM: C[M,128] = A[M,K] @ B[K,128] ----------------
// MODE 0: C = acc (+bias)
// MODE 1: C = acc + bias + P[i1[row]] + Q[i2[row]]          (h = eA@Wef + bh + xd[dst] + xs[src])
// MODE 2: C = relu(acc + bias + P[i1[row]] + Q[i2[row]])    (z = relu(eA@W1c + b1 + ys[src] + yd[dst]))
// MODE 3: C = R[row] + (acc + bias) * 0.5                   (e_new = edge_attr + (z@W2 + b2)*0.5)
template <int MODE>
__global__ void __launch_bounds__(256) gemm_k(
    const float* __restrict__ A, int lda,
    const float* __restrict__ B,
    const float* __restrict__ bias,
    float* __restrict__ C, int M, int K,
    const int* __restrict__ i1, const int* __restrict__ i2,
    const float* __restrict__ P, const float* __restrict__ Q,
    const float* __restrict__ R)
{
    __shared__ float As[16][128];
    __shared__ float Bs[16][128];
    const int tid = threadIdx.x;
    const int tx = tid & 15;
    const int ty = tid >> 4;
    const int row0 = blockIdx.x * 128;

    float acc[8][8];
#pragma unroll
    for (int i = 0; i < 8; i++)
#pragma unroll
        for (int j = 0; j < 8; j++) acc[i][j] = 0.f;

    for (int kk = 0; kk < K; kk += 16) {
#pragma unroll
        for (int it = 0; it < 2; it++) {
            int idx = tid + it * 256;        // 0..511
            int m = idx >> 2;
            int k4 = (idx & 3) << 2;
            int row = row0 + m;
            float4 v = make_float4(0.f, 0.f, 0.f, 0.f);
            if (row < M) v = *(const float4*)(A + (long)row * lda + kk + k4);
            As[k4 + 0][m] = v.x;
            As[k4 + 1][m] = v.y;
            As[k4 + 2][m] = v.z;
            As[k4 + 3][m] = v.w;
        }
#pragma unroll
        for (int it = 0; it < 2; it++) {
            int idx = tid + it * 256;
            int kb = idx >> 5;
            int n4 = (idx & 31) << 2;
            *(float4*)&Bs[kb][n4] = *(const float4*)(B + (long)(kk + kb) * 128 + n4);
        }
        __syncthreads();
#pragma unroll
        for (int k = 0; k < 16; k++) {
            float4 a0 = *(const float4*)&As[k][ty * 8];
            float4 a1 = *(const float4*)&As[k][ty * 8 + 4];
            float4 b0 = *(const float4*)&Bs[k][tx * 8];
            float4 b1 = *(const float4*)&Bs[k][tx * 8 + 4];
            float av[8] = {a0.x, a0.y, a0.z, a0.w, a1.x, a1.y, a1.z, a1.w};
            float bv[8] = {b0.x, b0.y, b0.z, b0.w, b1.x, b1.y, b1.z, b1.w};
#pragma unroll
            for (int i = 0; i < 8; i++)
#pragma unroll
                for (int j = 0; j < 8; j++) acc[i][j] += av[i] * bv[j];
        }
        __syncthreads();
    }

    const int col0 = tx * 8;
#pragma unroll
    for (int i = 0; i < 8; i++) {
        int row = row0 + ty * 8 + i;
        if (row >= M) continue;
        float* crow = C + (long)row * 128 + col0;
        if (MODE == 0) {
#pragma unroll
            for (int j = 0; j < 8; j++) {
                float v = acc[i][j];
                if (bias) v += bias[col0 + j];
                crow[j] = v;
            }
        } else if (MODE == 1 || MODE == 2) {
            int a = i1[row], b = i2[row];
            const float* Pr = P + (long)a * 128 + col0;
            const float* Qr = Q + (long)b * 128 + col0;
#pragma unroll
            for (int j = 0; j < 8; j++) {
                float v = acc[i][j] + bias[col0 + j] + Pr[j] + Qr[j];
                if (MODE == 2) v = fmaxf(v, 0.f);
                crow[j] = v;
            }
        } else { // MODE 3
            const float* Rr = R + (long)row * 128 + col0;
#pragma unroll
            for (int j = 0; j < 8; j++)
                crow[j] = Rr[j] + (acc[i][j] + bias[col0 + j]) * 0.5f;
        }
    }
}

// ---------------- small kernels ----------------
__global__ void zero_k() {
    int i = blockIdx.x * blockDim.x + threadIdx.x;
    if (i < N_NODES) g_deg[i] = 0;
    if (i < H) { g_bnsum[i] = 0.f; g_bnsq[i] = 0.f; }
}

__global__ void foldbias_k(const float* __restrict__ be, const float* __restrict__ bpre,
                           const float* __restrict__ Wpre, const float* __restrict__ bpost,
                           const float* __restrict__ blin, const float* __restrict__ Wlin) {
    int j = threadIdx.x; // 128
    float s = bpre[j];
    for (int k = 0; k < H; k++) s += be[k] * Wpre[(2 * H + k) * H + j];
    g_bh[j] = s;
    float t = blin[j];
    for (int k = 0; k < H; k++) t += bpost[k] * Wlin[k * H + j];
    g_b13[j] = t;
}

__global__ void hist_k(const int* __restrict__ dst) {
    int e = blockIdx.x * blockDim.x + threadIdx.x;
    if (e < N_EDGES) atomicAdd(&g_deg[dst[e]], 1);
}

__global__ void scan_k() {
    const int CH = 49; // 1024*49 >= 50000
    int t = threadIdx.x;
    int begin = t * CH;
    int end = min(begin + CH, N_NODES);
    int s = 0;
    for (int i = begin; i < end; i++) s += g_deg[i];
    __shared__ int sums[1024];
    sums[t] = s;
    __syncthreads();
    for (int off = 1; off < 1024; off <<= 1) {
        int v = (t >= off) ? sums[t - off] : 0;
        __syncthreads();
        sums[t] += v;
        __syncthreads();
    }
    int running = (t == 0) ? 0 : sums[t - 1];
    for (int i = begin; i < end; i++) {
        g_off[i] = running;
        g_cur[i] = running;
        running += g_deg[i];
    }
    if (t == 1023) g_off[N_NODES] = sums[1023];
}

__global__ void scatter_k(const int* __restrict__ dst) {
    int e = blockIdx.x * blockDim.x + threadIdx.x;
    if (e < N_EDGES) {
        int p = atomicAdd(&g_cur[dst[e]], 1);
        g_perm[p] = e;
    }
}

// per-node PNA aggregation; writes full A13 row (x copy + 12H scaled aggregates)
__global__ void reduce_k(const float* __restrict__ h, const float* __restrict__ x,
                         float* __restrict__ A13) {
    int node = blockIdx.x;
    int c = threadIdx.x; // 128
    int s = g_off[node], e = g_off[node + 1];
    float sum = 0.f, sum2 = 0.f, mx = -INFINITY, mn = INFINITY;
    for (int i = s; i < e; i++) {
        int ed = g_perm[i];
        float v = h[(long)ed * 128 + c];
        sum += v;
        sum2 += v * v;
        mx = fmaxf(mx, v);
        mn = fminf(mn, v);
    }
    int deg = e - s;
    float degc = fmaxf((float)deg, 1.f);
    float mean = sum / degc;
    float mean2 = sum2 / degc;
    float sd = sqrtf(fmaxf(mean2 - mean * mean, 0.f) + 1e-5f);
    if (deg == 0) { mx = 0.f; mn = 0.f; }
    float logd = logf(degc + 1.f);
    float s1 = logd / LOG17;
    float s2 = LOG17 / logd;
    float* row = A13 + (long)node * H13;
    row[c] = x[(long)node * 128 + c];
    row[128 + c] = mean;
    row[256 + c] = mx;
    row[384 + c] = mn;
    row[512 + c] = sd;
    row[640 + c] = mean * s1;
    row[768 + c] = mx * s1;
    row[896 + c] = mn * s1;
    row[1024 + c] = sd * s1;
    row[1152 + c] = mean * s2;
    row[1280 + c] = mx * s2;
    row[1408 + c] = mn * s2;
    row[1536 + c] = sd * s2;
}

__global__ void bn_partial_k(const float* __restrict__ out) {
    int c = threadIdx.x; // 128
    float s = 0.f, s2 = 0.f;
    for (int r = blockIdx.x; r < N_NODES; r += gridDim.x) {
        float v = out[(long)r * 128 + c];
        s += v;
        s2 += v * v;
    }
    atomicAdd(&g_bnsum[c], s);
    atomicAdd(&g_bnsq[c], s2);
}

__global__ void bn_final_k() {
    int c = threadIdx.x;
    float mu = g_bnsum[c] / (float)N_NODES;
    float var = g_bnsq[c] / (float)N_NODES - mu * mu;
    g_mu[c] = mu;
    g_istd[c] = rsqrtf(var + 1e-5f);
}

__global__ void xnew_k(const float* __restrict__ out, const float* __restrict__ x,
                       const float* __restrict__ gam, const float* __restrict__ bet,
                       float* __restrict__ xnew) {
    long i = (long)blockIdx.x * blockDim.x + threadIdx.x;
    if (i >= (long)N_NODES * H) return;
    int c = (int)(i & 127);
    float v = (out[i] - g_mu[c]) * g_istd[c] * gam[c] + bet[c];
    xnew[i] = 0.5f * (x[i] + fmaxf(v, 0.f));
}

// ---------------- launch ----------------
extern "C" void kernel_launch(void* const* d_in, const int* in_sizes, int n_in,
                              void* d_out, int out_size) {
    const float* x      = (const float*)d_in[0];
    const float* eattr  = (const float*)d_in[1];
    const float* We     = (const float*)d_in[2];
    const float* be     = (const float*)d_in[3];
    const float* Wpre   = (const float*)d_in[4];
    const float* bpre   = (const float*)d_in[5];
    const float* Wpost  = (const float*)d_in[6];
    const float* bpost  = (const float*)d_in[7];
    const float* Wlin   = (const float*)d_in[8];
    const float* blin   = (const float*)d_in[9];
    const float* bn_g   = (const float*)d_in[10];
    const float* bn_b   = (const float*)d_in[11];
    const float* W1     = (const float*)d_in[12];
    const float* b1     = (const float*)d_in[13];
    const float* W2     = (const float*)d_in[14];
    const float* b2     = (const float*)d_in[15];
    const int*   eidx   = (const int*)d_in[16];
    const int* src = eidx;
    const int* dst = eidx + N_EDGES;

    float* o = (float*)d_out;
    float* o_x = o;                         // x_new [N,H]
    float* o_e = o + (long)N_NODES * H;     // e_new [E,H]

    float *xd, *xs, *h, *A13, *outb, *Wef, *W13, *bh, *b13;
    cudaGetSymbolAddress((void**)&xd, g_xd);
    cudaGetSymbolAddress((void**)&xs, g_xs);
    cudaGetSymbolAddress((void**)&h, g_h);
    cudaGetSymbolAddress((void**)&A13, g_A13);
    cudaGetSymbolAddress((void**)&outb, g_outb);
    cudaGetSymbolAddress((void**)&Wef, g_Wef);
    cudaGetSymbolAddress((void**)&W13, g_W13);
    cudaGetSymbolAddress((void**)&bh, g_bh);
    cudaGetSymbolAddress((void**)&b13, g_b13);

    const int GN = (N_NODES + 127) / 128;   // 391
    const int GE = (N_EDGES + 127) / 128;   // 4688
    const int TE = (N_EDGES + 255) / 256;

    // 0) zero counters
    zero_k<<<(N_NODES + 255) / 256, 256>>>();
    // 1) fold biases + weights
    foldbias_k<<<1, 128>>>(be, bpre, Wpre, bpost, blin, Wlin);
    gemm_k<0><<<1, 256>>>(We, H, Wpre + 2 * H * H, nullptr, Wef, H, H,
                          nullptr, nullptr, nullptr, nullptr, nullptr);
    gemm_k<0><<<13, 256>>>(Wpost, H, Wlin, nullptr, W13, H13, H,
                           nullptr, nullptr, nullptr, nullptr, nullptr);
    // 2) node pre-projections
    gemm_k<0><<<GN, 256>>>(x, H, Wpre, nullptr, xd, N_NODES, H,
                           nullptr, nullptr, nullptr, nullptr, nullptr);
    gemm_k<0><<<GN, 256>>>(x, H, Wpre + H * H, nullptr, xs, N_NODES, H,
                           nullptr, nullptr, nullptr, nullptr, nullptr);
    // 3) dst-CSR
    hist_k<<<TE, 256>>>(dst);
    scan_k<<<1, 1024>>>();
    scatter_k<<<TE, 256>>>(dst);
    // 4) h = edge_attr @ Wef + bh + xd[dst] + xs[src]
    gemm_k<1><<<GE, 256>>>(eattr, H, Wef, bh, h, N_EDGES, H,
                           dst, src, xd, xs, nullptr);
    // 5) PNA aggregation -> A13
    reduce_k<<<N_NODES, 128>>>(h, x, A13);
    // 6) out = A13 @ W13 + b13
    gemm_k<0><<<GN, 256>>>(A13, H13, W13, b13, outb, N_NODES, H13,
                           nullptr, nullptr, nullptr, nullptr, nullptr);
    // 7) BN + relu + residual -> x_new (into d_out)
    bn_partial_k<<<256, 128>>>(outb);
    bn_final_k<<<1, 128>>>();
    xnew_k<<<(N_NODES * H + 255) / 256, 256>>>(outb, x, bn_g, bn_b, o_x);
    // 8) edge-update node projections (reuse xd/xs as ys/yd)
    gemm_k<0><<<GN, 256>>>(o_x, H, W1, nullptr, xd, N_NODES, H,
                           nullptr, nullptr, nullptr, nullptr, nullptr);
    gemm_k<0><<<GN, 256>>>(o_x, H, W1 + H * H, nullptr, xs, N_NODES, H,
                           nullptr, nullptr, nullptr, nullptr, nullptr);
    // 9) z = relu(edge_attr @ W1[2H:] + b1 + ys[src] + yd[dst]) (reuse h)
    gemm_k<2><<<GE, 256>>>(eattr, H, W1 + 2 * H * H, b1, h, N_EDGES, H,
                           src, dst, xd, xs, nullptr);
    // 10) e_new = edge_attr + (z @ W2 + b2) * 0.5
    gemm_k<3><<<GE, 256>>>(h, H, W2, b2, o_e, N_EDGES, H,
                           nullptr, nullptr, nullptr, nullptr, eattr);
    (void)in_sizes; (void)n_in; (void)out_size;
}